// round 9
// baseline (speedup 1.0000x reference)
#include <cuda_runtime.h>
#include <cuda_fp16.h>
#include <cstdint>

#define NL 4
#define TT 64
#define PAIRS 4
#define THREADS (PAIRS * 64)         // 256: 4 warp pairs
#define ROWS_CTA (PAIRS * 32)        // 128 (32 rows per pair, two m16 tiles)
#define BTOT 16384

// SMEM offsets
#define OFF_BIAS 65536u
#define OFF_HX   67584u              // PAIRS * NL * 4096 = 65536
#define OFF_RED  133120u             // PAIRS * 256
#define DSMEM    (133120 + 1024 + 64)

// staged data (built by prep_kernel)
__device__ uint32_t gBF[16384];      // fp16 W fragments [l][kc][nt][lane][word] (64KB)
__device__ float    gBiasF[512];
__device__ float    gWl[32];
__device__ float    gBl;

// ---------------- helpers ----------------
__device__ __forceinline__ uint32_t smem_u32(const void* p) {
    uint32_t a;
    asm("{ .reg .u64 t; cvta.to.shared.u64 t, %1; cvt.u32.u64 %0, t; }" : "=r"(a) : "l"(p));
    return a;
}
__device__ __forceinline__ void mma16816(float d[4], const uint32_t a[4], uint32_t b0, uint32_t b1) {
    asm volatile("mma.sync.aligned.m16n8k16.row.col.f32.f16.f16.f32 "
                 "{%0,%1,%2,%3}, {%4,%5,%6,%7}, {%8,%9}, {%0,%1,%2,%3};"
                 : "+f"(d[0]), "+f"(d[1]), "+f"(d[2]), "+f"(d[3])
                 : "r"(a[0]), "r"(a[1]), "r"(a[2]), "r"(a[3]), "r"(b0), "r"(b1));
}
__device__ __forceinline__ void lds64(uint32_t& a, uint32_t& b, uint32_t addr) {
    asm volatile("ld.shared.v2.u32 {%0,%1}, [%2];" : "=r"(a), "=r"(b) : "r"(addr));
}
__device__ __forceinline__ float2 ldsf2(uint32_t addr) {
    float2 v;
    asm volatile("ld.shared.v2.f32 {%0,%1}, [%2];" : "=f"(v.x), "=f"(v.y) : "r"(addr));
    return v;
}
__device__ __forceinline__ void ld8(uint32_t* f, uint32_t addr) {
    asm volatile("ld.shared.v4.u32 {%0,%1,%2,%3}, [%4];"
                 : "=r"(f[0]), "=r"(f[1]), "=r"(f[2]), "=r"(f[3]) : "r"(addr));
    asm volatile("ld.shared.v4.u32 {%0,%1,%2,%3}, [%4];"
                 : "=r"(f[4]), "=r"(f[5]), "=r"(f[6]), "=r"(f[7]) : "r"(addr + 16u));
}
__device__ __forceinline__ void st8(uint32_t addr, const uint32_t* f) {
    asm volatile("st.shared.v4.u32 [%0], {%1,%2,%3,%4};"
                 :: "r"(addr), "r"(f[0]), "r"(f[1]), "r"(f[2]), "r"(f[3]) : "memory");
    asm volatile("st.shared.v4.u32 [%0], {%1,%2,%3,%4};"
                 :: "r"(addr + 16u), "r"(f[4]), "r"(f[5]), "r"(f[6]), "r"(f[7]) : "memory");
}
__device__ __forceinline__ void stsf(uint32_t addr, float v) {
    asm volatile("st.shared.f32 [%0], %1;" :: "r"(addr), "f"(v) : "memory");
}
__device__ __forceinline__ float ldsf(uint32_t addr) {
    float v; asm volatile("ld.shared.f32 %0, [%1];" : "=f"(v) : "r"(addr)); return v;
}
#define BARP(id) asm volatile("bar.sync %0, 64;" :: "r"(id) : "memory")

__device__ __forceinline__ float hfhi(float v) { return __half2float(__float2half_rn(v)); }
__device__ __forceinline__ uint32_t pkhf(float lo, float hi) {
    __half2 t = __floats2half2_rn(lo, hi);
    return *(uint32_t*)&t;
}
__device__ __forceinline__ float tanh_apx(float v) {
    float r; asm("tanh.approx.f32 %0, %1;" : "=f"(r) : "f"(v)); return r;
}
__device__ __forceinline__ float sigm_apx(float v) {
    return fmaf(0.5f, tanh_apx(0.5f * v), 0.5f);
}
__device__ __forceinline__ float sigm_ex(float v) {
    return __fdividef(1.f, 1.f + __expf(-v));
}

// ---------------- prep ----------------
__device__ __forceinline__ float getW(const float* W_ih0, const float* W_ih, const float* W_hh,
                                      int l, int n, int k) {
    if (k < 32) {
        if (l == 0) return (k < 2) ? W_ih0[n * 2 + k] : 0.f;
        return W_ih[(l - 1) * 4096 + n * 32 + k];
    }
    return W_hh[l * 4096 + n * 32 + (k - 32)];
}

__global__ void prep_kernel(const float* __restrict__ W_ih0, const float* __restrict__ W_ih,
                            const float* __restrict__ W_hh, const float* __restrict__ b_ih,
                            const float* __restrict__ b_hh, const float* __restrict__ W_lin,
                            const float* __restrict__ b_lin) {
    int i = blockIdx.x * blockDim.x + threadIdx.x;
    if (i < 16384) {
        int word = i & 1, lane = (i >> 1) & 31, nt = (i >> 6) & 15, kc = (i >> 10) & 3, l = i >> 12;
        int n  = nt * 8 + (lane >> 2);
        int k0 = kc * 16 + (lane & 3) * 2 + word * 8;
        float w0 = getW(W_ih0, W_ih, W_hh, l, n, k0);
        float w1 = getW(W_ih0, W_ih, W_hh, l, n, k0 + 1);
        __half2 t = __floats2half2_rn(w0, w1);
        gBF[i] = *(uint32_t*)&t;
    }
    if (i < 512) {
        int e = i & 1, q = (i >> 1) & 3, nt = (i >> 3) & 15, l = i >> 7;
        int n = nt * 8 + q * 2 + e;
        gBiasF[i] = b_ih[l * 128 + n] + b_hh[l * 128 + n];
    }
    if (i < 32) gWl[i] = W_lin[i];
    if (i == 0) gBl = b_lin[0];
}

// ---- one k-chunk, both m-tiles, 2-term (zhi + zlo): 4 gate groups ----
// A[mt][0..3]=zhi frag, A[mt][4..7]=zlo frag
__device__ __forceinline__ void mma_chunk(float (&d)[2][4][4], const uint32_t A[2][8],
                                          uint32_t bKC, int jt) {
#pragma unroll
    for (int g4 = 0; g4 < 4; ++g4) {
        uint32_t b0, b1;
        lds64(b0, b1, bKC + (uint32_t)((g4 * 4 + jt) * 2) * 128u);
#pragma unroll
        for (int mt = 0; mt < 2; ++mt) {
            mma16816(d[mt][g4], A[mt],     b0, b1);
            mma16816(d[mt][g4], A[mt] + 4, b0, b1);
        }
    }
}

// ---------------- main kernel ----------------
__global__ void __launch_bounds__(THREADS, 1)
lstm_kernel(const float* __restrict__ x, float* __restrict__ out) {
    extern __shared__ __align__(16) uint4 smemraw[];
    const uint32_t smB   = smem_u32(smemraw);
    const uint32_t biasB = smB + OFF_BIAS;
    const uint32_t hxB   = smB + OFF_HX;
    const uint32_t redB  = smB + OFF_RED;

    const int tid  = threadIdx.x;
    const int w    = tid >> 5;
    const int lane = tid & 31;
    const int q    = lane & 3;
    const int r    = lane >> 2;
    const int pp   = w >> 1;            // pair id
    const int wh   = w & 1;             // gate-col half [16wh, 16wh+16); owns h chunk wh
    const int bid  = 1 + pp;
    const int gb0  = blockIdx.x * ROWS_CTA + pp * 32;

    // ---- stage weights + bias; zero hx ----
    {
        const uint4* src = (const uint4*)gBF;
        uint4* dst = (uint4*)smemraw;
        for (int i = tid; i < 4096; i += THREADS) dst[i] = src[i];
        float* bd = (float*)((char*)smemraw + OFF_BIAS);
        for (int i = tid; i < 512; i += THREADS) bd[i] = gBiasF[i];
        uint4* hz = (uint4*)((char*)smemraw + OFF_HX);
        for (int i = tid; i < 65536 / 16; i += THREADS) hz[i] = make_uint4(0, 0, 0, 0);
    }
    __syncthreads();

    float cst[NL][2][2][4];             // [l][jl][mt][p]
#pragma unroll
    for (int l = 0; l < NL; ++l)
#pragma unroll
        for (int jl = 0; jl < 2; ++jl)
#pragma unroll
            for (int mt = 0; mt < 2; ++mt)
#pragma unroll
                for (int p = 0; p < 4; ++p) cst[l][jl][mt][p] = 0.f;

    float wl[2][2];
#pragma unroll
    for (int jl = 0; jl < 2; ++jl) {
        int jt = wh * 2 + jl;
        wl[jl][0] = gWl[jt * 8 + q * 2];
        wl[jl][1] = gWl[jt * 8 + q * 2 + 1];
    }

    const float* xq = x + (size_t)gb0 * 192;
    float prow[2][2] = {{0.f, 0.f}, {0.f, 0.f}};    // [mt][r / r+8]
    const uint32_t hxPair = hxB + (uint32_t)(pp * NL) * 4096u + (uint32_t)lane * 32u;

#pragma unroll 1
    for (int t = 0; t < TT; ++t) {
        // ---- x fragments (layer 0, kc0): cols 0,1 in q==0 lanes; two m-tiles ----
        uint32_t AX[2][8];
#pragma unroll
        for (int mt = 0; mt < 2; ++mt)
#pragma unroll
            for (int u = 0; u < 8; ++u) AX[mt][u] = 0u;
        if (q == 0) {
#pragma unroll
            for (int mt = 0; mt < 2; ++mt) {
                const float* xr = xq + (size_t)(mt * 16 + r) * 192 + t;
                float x0a = __ldg(xr),        x1a = __ldg(xr + 64);
                float x0b = __ldg(xr + 1536), x1b = __ldg(xr + 1600);   // row +8
                float e0 = hfhi(x0a), e1 = hfhi(x1a), e2 = hfhi(x0b), e3 = hfhi(x1b);
                AX[mt][0] = pkhf(e0, e1);             AX[mt][1] = pkhf(e2, e3);
                AX[mt][4] = pkhf(x0a - e0, x1a - e1); AX[mt][5] = pkhf(x0b - e2, x1b - e3);
            }
        }

#pragma unroll
        for (int l = 0; l < NL; ++l) {
            const uint32_t hxL = hxPair + (uint32_t)l * 4096u;
            uint32_t hin[2][2][8], hp[2][2][8];     // [chunk][mt][8]
            if (l > 0) {
#pragma unroll
                for (int ch = 0; ch < 2; ++ch)
#pragma unroll
                    for (int mt = 0; mt < 2; ++mt)
                        ld8(hin[ch][mt], hxL - 4096u + (uint32_t)(ch * 2048 + mt * 1024));
            }
#pragma unroll
            for (int ch = 0; ch < 2; ++ch)
#pragma unroll
                for (int mt = 0; mt < 2; ++mt)
                    ld8(hp[ch][mt], hxL + (uint32_t)(ch * 2048 + mt * 1024));

            float hh[2][2][4];                       // [jl][mt][p]
#pragma unroll
            for (int jl = 0; jl < 2; ++jl) {
                const int jt = wh * 2 + jl;
                float d[2][4][4];
#pragma unroll
                for (int g4 = 0; g4 < 4; ++g4) {
                    float2 bb = ldsf2(biasB + (uint32_t)(((l * 16 + g4 * 4 + jt) * 4 + q) * 8));
#pragma unroll
                    for (int mt = 0; mt < 2; ++mt) {
                        d[mt][g4][0] = bb.x; d[mt][g4][1] = bb.y;
                        d[mt][g4][2] = bb.x; d[mt][g4][3] = bb.y;
                    }
                }
                const uint32_t bL = smB + (uint32_t)l * 16384u + (uint32_t)lane * 8u;
                if (l == 0) {
                    mma_chunk(d, AX, bL, jt);                        // x (kc0)
                } else {
                    mma_chunk(d, hin[0], bL,          jt);           // h_in kc0
                    mma_chunk(d, hin[1], bL + 4096u,  jt);           // h_in kc1
                }
                mma_chunk(d, hp[0], bL + 8192u,  jt);                // h_prev kc2
                mma_chunk(d, hp[1], bL + 12288u, jt);                // h_prev kc3

#pragma unroll
                for (int mt = 0; mt < 2; ++mt)
#pragma unroll
                    for (int p = 0; p < 4; ++p) {
                        float ii = sigm_apx(d[mt][0][p]);
                        float ff = sigm_apx(d[mt][1][p]);
                        float gg = tanh_apx(d[mt][2][p]);
                        float oo = sigm_apx(d[mt][3][p]);
                        float cn = fmaf(ff, cst[l][jl][mt][p], ii * gg);
                        cst[l][jl][mt][p] = cn;
                        float hv = oo * tanh_apx(cn);
                        hh[jl][mt][p] = hv;
                        if (l == NL - 1 && t == TT - 1)
                            prow[mt][p >> 1] = fmaf(hv, wl[jl][p & 1], prow[mt][p >> 1]);
                    }
            }

            BARP(bid);   // partner finished reading this layer's h_prev
#pragma unroll
            for (int mt = 0; mt < 2; ++mt) {
                uint32_t fr[8];
#pragma unroll
                for (int rr = 0; rr < 4; ++rr) {
                    int jl = rr >> 1, p0 = (rr & 1) * 2;
                    float h0 = hh[jl][mt][p0], h1 = hh[jl][mt][p0 + 1];
                    float e0 = hfhi(h0), e1 = hfhi(h1);
                    fr[rr]     = pkhf(e0, e1);
                    fr[4 + rr] = pkhf(h0 - e0, h1 - e1);
                }
                st8(hxL + (uint32_t)(wh * 2048 + mt * 1024), fr);
            }
            BARP(bid);   // publish h_new
        }
    }

    // ---- head: out = sigmoid(h3 . Wlin + b) ----
#pragma unroll
    for (int mt = 0; mt < 2; ++mt)
#pragma unroll
        for (int hb = 0; hb < 2; ++hb) {
            prow[mt][hb] += __shfl_xor_sync(0xffffffffu, prow[mt][hb], 1);
            prow[mt][hb] += __shfl_xor_sync(0xffffffffu, prow[mt][hb], 2);
        }
    const uint32_t redP = redB + (uint32_t)(pp * 256);
    if (q == 0) {
#pragma unroll
        for (int mt = 0; mt < 2; ++mt) {
            stsf(redP + (uint32_t)(wh * 128 + (mt * 16 + r) * 4),     prow[mt][0]);
            stsf(redP + (uint32_t)(wh * 128 + (mt * 16 + r + 8) * 4), prow[mt][1]);
        }
    }
    BARP(bid);
    if (wh == 0 && q == 0) {
        float bl = gBl;
#pragma unroll
        for (int mt = 0; mt < 2; ++mt) {
#pragma unroll
            for (int hb = 0; hb < 2; ++hb) {
                int row = mt * 16 + r + hb * 8;
                float v = ldsf(redP + (uint32_t)(row * 4)) + ldsf(redP + (uint32_t)(128 + row * 4));
                out[gb0 + row] = sigm_ex(v + bl);
            }
        }
    }
}

extern "C" void kernel_launch(void* const* d_in, const int* in_sizes, int n_in,
                              void* d_out, int out_size) {
    const float* x     = (const float*)d_in[0];
    const float* W_ih0 = (const float*)d_in[1];
    const float* W_ih  = (const float*)d_in[2];
    const float* W_hh  = (const float*)d_in[3];
    const float* b_ih  = (const float*)d_in[4];
    const float* b_hh  = (const float*)d_in[5];
    const float* W_lin = (const float*)d_in[6];
    const float* b_lin = (const float*)d_in[7];

    prep_kernel<<<64, 256>>>(W_ih0, W_ih, W_hh, b_ih, b_hh, W_lin, b_lin);

    cudaFuncSetAttribute(lstm_kernel, cudaFuncAttributeMaxDynamicSharedMemorySize, DSMEM);

    int blocks = BTOT / ROWS_CTA;    // 128
    lstm_kernel<<<blocks, THREADS, DSMEM>>>(x, (float*)d_out);
}

// round 10
// speedup vs baseline: 1.6636x; 1.6636x over previous
#include <cuda_runtime.h>
#include <cuda_fp16.h>
#include <cstdint>

#define NL 4
#define TT 64
#define PAIRS 7
#define THREADS (PAIRS * 64)         // 448: 7 warp pairs, 16 rows each
#define ROWS_CTA (PAIRS * 16)        // 112
#define BTOT 16384

// SMEM offsets
#define OFF_BIAS 65536u
#define OFF_HX   67584u              // PAIRS*NL*2 chunks * 1KB = 57344
#define OFF_RED  124928u             // PAIRS*2*16 floats = 896
#define DSMEM    (124928 + 896 + 64)

// staged data (built by prep_kernel)
__device__ uint32_t gBF[16384];      // fp16 W fragments [l][kc][nt][lane][word] (64KB)
__device__ float    gBiasF[512];
__device__ float    gWl[32];
__device__ float    gBl;

// ---------------- helpers ----------------
__device__ __forceinline__ uint32_t smem_u32(const void* p) {
    uint32_t a;
    asm("{ .reg .u64 t; cvta.to.shared.u64 t, %1; cvt.u32.u64 %0, t; }" : "=r"(a) : "l"(p));
    return a;
}
__device__ __forceinline__ void mma16816(float d[4], const uint32_t a[4], uint32_t b0, uint32_t b1) {
    asm volatile("mma.sync.aligned.m16n8k16.row.col.f32.f16.f16.f32 "
                 "{%0,%1,%2,%3}, {%4,%5,%6,%7}, {%8,%9}, {%0,%1,%2,%3};"
                 : "+f"(d[0]), "+f"(d[1]), "+f"(d[2]), "+f"(d[3])
                 : "r"(a[0]), "r"(a[1]), "r"(a[2]), "r"(a[3]), "r"(b0), "r"(b1));
}
__device__ __forceinline__ void lds64(uint32_t& a, uint32_t& b, uint32_t addr) {
    asm volatile("ld.shared.v2.u32 {%0,%1}, [%2];" : "=r"(a), "=r"(b) : "r"(addr));
}
__device__ __forceinline__ float2 ldsf2(uint32_t addr) {
    float2 v;
    asm volatile("ld.shared.v2.f32 {%0,%1}, [%2];" : "=f"(v.x), "=f"(v.y) : "r"(addr));
    return v;
}
__device__ __forceinline__ void ld8(uint32_t* f, uint32_t addr) {
    asm volatile("ld.shared.v4.u32 {%0,%1,%2,%3}, [%4];"
                 : "=r"(f[0]), "=r"(f[1]), "=r"(f[2]), "=r"(f[3]) : "r"(addr));
    asm volatile("ld.shared.v4.u32 {%0,%1,%2,%3}, [%4];"
                 : "=r"(f[4]), "=r"(f[5]), "=r"(f[6]), "=r"(f[7]) : "r"(addr + 16u));
}
__device__ __forceinline__ void st8(uint32_t addr, const uint32_t* f) {
    asm volatile("st.shared.v4.u32 [%0], {%1,%2,%3,%4};"
                 :: "r"(addr), "r"(f[0]), "r"(f[1]), "r"(f[2]), "r"(f[3]) : "memory");
    asm volatile("st.shared.v4.u32 [%0], {%1,%2,%3,%4};"
                 :: "r"(addr + 16u), "r"(f[4]), "r"(f[5]), "r"(f[6]), "r"(f[7]) : "memory");
}
__device__ __forceinline__ void stsf(uint32_t addr, float v) {
    asm volatile("st.shared.f32 [%0], %1;" :: "r"(addr), "f"(v) : "memory");
}
__device__ __forceinline__ float ldsf(uint32_t addr) {
    float v; asm volatile("ld.shared.f32 %0, [%1];" : "=f"(v) : "r"(addr)); return v;
}
#define BARP(id) asm volatile("bar.sync %0, 64;" :: "r"(id) : "memory")

__device__ __forceinline__ float hfhi(float v) { return __half2float(__float2half_rn(v)); }
__device__ __forceinline__ uint32_t pkhf(float lo, float hi) {
    __half2 t = __floats2half2_rn(lo, hi);
    return *(uint32_t*)&t;
}
__device__ __forceinline__ float tanh_apx(float v) {
    float r; asm("tanh.approx.f32 %0, %1;" : "=f"(r) : "f"(v)); return r;
}
__device__ __forceinline__ float sigm_apx(float v) {
    return fmaf(0.5f, tanh_apx(0.5f * v), 0.5f);
}
__device__ __forceinline__ float sigm_ex(float v) {
    return __fdividef(1.f, 1.f + __expf(-v));
}

// ---------------- prep ----------------
__device__ __forceinline__ float getW(const float* W_ih0, const float* W_ih, const float* W_hh,
                                      int l, int n, int k) {
    if (k < 32) {
        if (l == 0) return (k < 2) ? W_ih0[n * 2 + k] : 0.f;
        return W_ih[(l - 1) * 4096 + n * 32 + k];
    }
    return W_hh[l * 4096 + n * 32 + (k - 32)];
}

__global__ void prep_kernel(const float* __restrict__ W_ih0, const float* __restrict__ W_ih,
                            const float* __restrict__ W_hh, const float* __restrict__ b_ih,
                            const float* __restrict__ b_hh, const float* __restrict__ W_lin,
                            const float* __restrict__ b_lin) {
    int i = blockIdx.x * blockDim.x + threadIdx.x;
    if (i < 16384) {
        int word = i & 1, lane = (i >> 1) & 31, nt = (i >> 6) & 15, kc = (i >> 10) & 3, l = i >> 12;
        int n  = nt * 8 + (lane >> 2);
        int k0 = kc * 16 + (lane & 3) * 2 + word * 8;
        float w0 = getW(W_ih0, W_ih, W_hh, l, n, k0);
        float w1 = getW(W_ih0, W_ih, W_hh, l, n, k0 + 1);
        __half2 t = __floats2half2_rn(w0, w1);
        gBF[i] = *(uint32_t*)&t;
    }
    if (i < 512) {
        int e = i & 1, q = (i >> 1) & 3, nt = (i >> 3) & 15, l = i >> 7;
        int n = nt * 8 + q * 2 + e;
        gBiasF[i] = b_ih[l * 128 + n] + b_hh[l * 128 + n];
    }
    if (i < 32) gWl[i] = W_lin[i];
    if (i == 0) gBl = b_lin[0];
}

// ---- one k-chunk: 4 gate n-tiles, 2-term (zhi + zlo) fp16 ----
__device__ __forceinline__ void mma_chunk(float (&d)[4][4], const uint32_t* ahi, const uint32_t* alo,
                                          uint32_t bKC, int jt) {
#pragma unroll
    for (int g4 = 0; g4 < 4; ++g4) {
        uint32_t b0, b1;
        lds64(b0, b1, bKC + (uint32_t)((g4 * 4 + jt) * 256));
        mma16816(d[g4], ahi, b0, b1);
        mma16816(d[g4], alo, b0, b1);
    }
}

// ---------------- main kernel ----------------
__global__ void __launch_bounds__(THREADS, 1)
lstm_kernel(const float* __restrict__ x, float* __restrict__ out) {
    extern __shared__ __align__(16) uint4 smemraw[];
    const uint32_t smB   = smem_u32(smemraw);
    const uint32_t biasB = smB + OFF_BIAS;
    const uint32_t hxB   = smB + OFF_HX;
    const uint32_t redB  = smB + OFF_RED;

    const int tid  = threadIdx.x;
    const int w    = tid >> 5;
    const int lane = tid & 31;
    const int q    = lane & 3;
    const int r    = lane >> 2;
    const int pp   = w >> 1;            // pair id
    const int wh   = w & 1;             // gate-col half [16wh,16wh+16); owns h chunk wh
    const int bid  = 1 + pp;            // named barrier id
    const int gb0  = blockIdx.x * ROWS_CTA + pp * 16;

    // ---- stage weights + bias; zero hx ----
    {
        const uint4* src = (const uint4*)gBF;
        uint4* dst = (uint4*)smemraw;
        for (int i = tid; i < 4096; i += THREADS) dst[i] = src[i];
        float* bd = (float*)((char*)smemraw + OFF_BIAS);
        for (int i = tid; i < 512; i += THREADS) bd[i] = gBiasF[i];
        uint4* hz = (uint4*)((char*)smemraw + OFF_HX);
        for (int i = tid; i < 57344 / 16; i += THREADS) hz[i] = make_uint4(0, 0, 0, 0);
    }
    __syncthreads();
    if (gb0 >= BTOT) return;

    float cst[NL][2][4];
#pragma unroll
    for (int l = 0; l < NL; ++l)
#pragma unroll
        for (int jl = 0; jl < 2; ++jl)
#pragma unroll
            for (int p = 0; p < 4; ++p) cst[l][jl][p] = 0.f;

    float wl[2][2];
#pragma unroll
    for (int jl = 0; jl < 2; ++jl) {
        int jt = wh * 2 + jl;
        wl[jl][0] = gWl[jt * 8 + q * 2];
        wl[jl][1] = gWl[jt * 8 + q * 2 + 1];
    }

    const float* xq = x + (size_t)(gb0 + r) * 192;
    float prow0 = 0.f, prow8 = 0.f;
    const uint32_t hxPair = hxB + (uint32_t)(pp * NL * 2) * 1024u + (uint32_t)lane * 32u;

#pragma unroll 1
    for (int t = 0; t < TT; ++t) {
        // ---- x fragment (layer 0, kc0): cols 0,1 live in q==0 lanes ----
        uint32_t axh[4] = {0u, 0u, 0u, 0u}, axl[4] = {0u, 0u, 0u, 0u};
        if (q == 0) {
            float x0a = __ldg(xq + t),        x1a = __ldg(xq + 64 + t);
            float x0b = __ldg(xq + 1536 + t), x1b = __ldg(xq + 1600 + t);   // row+8
            float e0 = hfhi(x0a), e1 = hfhi(x1a), e2 = hfhi(x0b), e3 = hfhi(x1b);
            axh[0] = pkhf(e0, e1);             axh[1] = pkhf(e2, e3);
            axl[0] = pkhf(x0a - e0, x1a - e1); axl[1] = pkhf(x0b - e2, x1b - e3);
        }

#pragma unroll
        for (int l = 0; l < NL; ++l) {
            const uint32_t hxL = hxPair + (uint32_t)(l * 2) * 1024u;
            uint32_t hin0[8], hin1[8], hp0[8], hp1[8];   // [0..3]=zhi frag, [4..7]=zlo frag
            if (l > 0) {
                ld8(hin0, hxL - 2048u);
                ld8(hin1, hxL - 1024u);
            }
            ld8(hp0, hxL);
            ld8(hp1, hxL + 1024u);

            float hh[2][4];
#pragma unroll
            for (int jl = 0; jl < 2; ++jl) {
                const int jt = wh * 2 + jl;
                float d[4][4];
#pragma unroll
                for (int g4 = 0; g4 < 4; ++g4) {
                    float2 bb = ldsf2(biasB + (uint32_t)(((l * 16 + g4 * 4 + jt) * 4 + q) * 8));
                    d[g4][0] = bb.x; d[g4][1] = bb.y; d[g4][2] = bb.x; d[g4][3] = bb.y;
                }
                const uint32_t bL = smB + (uint32_t)l * 16384u + (uint32_t)lane * 8u;
                if (l == 0) {
                    mma_chunk(d, axh, axl, bL, jt);                     // x (kc0)
                } else {
                    mma_chunk(d, hin0, hin0 + 4, bL,         jt);       // h_in kc0
                    mma_chunk(d, hin1, hin1 + 4, bL + 4096u, jt);       // h_in kc1
                }
                mma_chunk(d, hp0, hp0 + 4, bL + 8192u,  jt);            // h_prev kc2
                mma_chunk(d, hp1, hp1 + 4, bL + 12288u, jt);            // h_prev kc3

#pragma unroll
                for (int p = 0; p < 4; ++p) {
                    float ii = sigm_apx(d[0][p]);
                    float ff = sigm_apx(d[1][p]);
                    float gg = tanh_apx(d[2][p]);
                    float oo = sigm_apx(d[3][p]);
                    float cn = fmaf(ff, cst[l][jl][p], ii * gg);
                    cst[l][jl][p] = cn;
                    float hv = oo * tanh_apx(cn);
                    hh[jl][p] = hv;
                    if (l == NL - 1 && t == TT - 1) {
                        if (p == 0) prow0 = fmaf(hv, wl[jl][0], prow0);
                        if (p == 1) prow0 = fmaf(hv, wl[jl][1], prow0);
                        if (p == 2) prow8 = fmaf(hv, wl[jl][0], prow8);
                        if (p == 3) prow8 = fmaf(hv, wl[jl][1], prow8);
                    }
                }
            }

            BARP(bid);   // partner finished reading hx[l] (h_prev)
            uint32_t fr[8];
#pragma unroll
            for (int rr = 0; rr < 4; ++rr) {
                int jl = rr >> 1, p0 = (rr & 1) * 2;
                float h0 = hh[jl][p0], h1 = hh[jl][p0 + 1];
                float e0 = hfhi(h0), e1 = hfhi(h1);
                fr[rr]     = pkhf(e0, e1);
                fr[4 + rr] = pkhf(h0 - e0, h1 - e1);
            }
            st8(hxL + (uint32_t)wh * 1024u, fr);
            BARP(bid);   // publish h_new for next layer / next step
        }
    }

    // ---- head: out = sigmoid(h3 . Wlin + b) ----
    prow0 += __shfl_xor_sync(0xffffffffu, prow0, 1);
    prow0 += __shfl_xor_sync(0xffffffffu, prow0, 2);
    prow8 += __shfl_xor_sync(0xffffffffu, prow8, 1);
    prow8 += __shfl_xor_sync(0xffffffffu, prow8, 2);
    const uint32_t redP = redB + (uint32_t)((pp * 2 + wh) * 64);
    if (q == 0) {
        stsf(redP + (uint32_t)r * 4, prow0);
        stsf(redP + (uint32_t)(r + 8) * 4, prow8);
    }
    BARP(bid);
    if (wh == 0 && q == 0) {
        float bl = gBl;
        float v0 = ldsf(redP + (uint32_t)r * 4)       + ldsf(redP + 64u + (uint32_t)r * 4);
        float v8 = ldsf(redP + (uint32_t)(r + 8) * 4) + ldsf(redP + 64u + (uint32_t)(r + 8) * 4);
        out[gb0 + r]     = sigm_ex(v0 + bl);
        out[gb0 + r + 8] = sigm_ex(v8 + bl);
    }
}

extern "C" void kernel_launch(void* const* d_in, const int* in_sizes, int n_in,
                              void* d_out, int out_size) {
    const float* x     = (const float*)d_in[0];
    const float* W_ih0 = (const float*)d_in[1];
    const float* W_ih  = (const float*)d_in[2];
    const float* W_hh  = (const float*)d_in[3];
    const float* b_ih  = (const float*)d_in[4];
    const float* b_hh  = (const float*)d_in[5];
    const float* W_lin = (const float*)d_in[6];
    const float* b_lin = (const float*)d_in[7];

    prep_kernel<<<64, 256>>>(W_ih0, W_ih, W_hh, b_ih, b_hh, W_lin, b_lin);

    cudaFuncSetAttribute(lstm_kernel, cudaFuncAttributeMaxDynamicSharedMemorySize, DSMEM);

    int blocks = (BTOT + ROWS_CTA - 1) / ROWS_CTA;    // 147
    lstm_kernel<<<blocks, THREADS, DSMEM>>>(x, (float*)d_out);
}

// round 11
// speedup vs baseline: 1.8694x; 1.1237x over previous
#include <cuda_runtime.h>
#include <cuda_fp16.h>
#include <cstdint>

#define NL 4
#define TT 64
#define PAIRS 7
#define THREADS (PAIRS * 64)         // 448: 7 warp pairs, 16 rows each
#define ROWS_CTA (PAIRS * 16)        // 112
#define BTOT 16384

// SMEM offsets
#define OFF_BIAS 65536u
#define OFF_HX   67584u              // PAIRS*NL*2 chunks * 1KB = 57344
#define OFF_RED  124928u             // PAIRS*2*16 floats = 896
#define DSMEM    (124928 + 896 + 64)

// staged data (built by prep_kernel)
__device__ uint32_t gBF[16384];      // fp16 W fragments [l][kc][nt][lane][word] (64KB)
__device__ float    gBiasF[512];
__device__ float    gWl[32];
__device__ float    gBl;

// ---------------- helpers ----------------
__device__ __forceinline__ uint32_t smem_u32(const void* p) {
    uint32_t a;
    asm("{ .reg .u64 t; cvta.to.shared.u64 t, %1; cvt.u32.u64 %0, t; }" : "=r"(a) : "l"(p));
    return a;
}
__device__ __forceinline__ void mma16816(float d[4], const uint32_t a[4], uint32_t b0, uint32_t b1) {
    asm volatile("mma.sync.aligned.m16n8k16.row.col.f32.f16.f16.f32 "
                 "{%0,%1,%2,%3}, {%4,%5,%6,%7}, {%8,%9}, {%0,%1,%2,%3};"
                 : "+f"(d[0]), "+f"(d[1]), "+f"(d[2]), "+f"(d[3])
                 : "r"(a[0]), "r"(a[1]), "r"(a[2]), "r"(a[3]), "r"(b0), "r"(b1));
}
__device__ __forceinline__ void lds64(uint32_t& a, uint32_t& b, uint32_t addr) {
    asm volatile("ld.shared.v2.u32 {%0,%1}, [%2];" : "=r"(a), "=r"(b) : "r"(addr));
}
__device__ __forceinline__ float2 ldsf2(uint32_t addr) {
    float2 v;
    asm volatile("ld.shared.v2.f32 {%0,%1}, [%2];" : "=f"(v.x), "=f"(v.y) : "r"(addr));
    return v;
}
// conflict-free fragment ld/st: two 512B halves, lane stride 16B
__device__ __forceinline__ void ldfrag(uint32_t* f, uint32_t chunkBase, uint32_t lane16) {
    asm volatile("ld.shared.v4.u32 {%0,%1,%2,%3}, [%4];"
                 : "=r"(f[0]), "=r"(f[1]), "=r"(f[2]), "=r"(f[3]) : "r"(chunkBase + lane16));
    asm volatile("ld.shared.v4.u32 {%0,%1,%2,%3}, [%4];"
                 : "=r"(f[4]), "=r"(f[5]), "=r"(f[6]), "=r"(f[7]) : "r"(chunkBase + 512u + lane16));
}
__device__ __forceinline__ void stfrag(uint32_t chunkBase, uint32_t lane16, const uint32_t* f) {
    asm volatile("st.shared.v4.u32 [%0], {%1,%2,%3,%4};"
                 :: "r"(chunkBase + lane16), "r"(f[0]), "r"(f[1]), "r"(f[2]), "r"(f[3]) : "memory");
    asm volatile("st.shared.v4.u32 [%0], {%1,%2,%3,%4};"
                 :: "r"(chunkBase + 512u + lane16), "r"(f[4]), "r"(f[5]), "r"(f[6]), "r"(f[7]) : "memory");
}
__device__ __forceinline__ void stsf(uint32_t addr, float v) {
    asm volatile("st.shared.f32 [%0], %1;" :: "r"(addr), "f"(v) : "memory");
}
__device__ __forceinline__ float ldsf(uint32_t addr) {
    float v; asm volatile("ld.shared.f32 %0, [%1];" : "=f"(v) : "r"(addr)); return v;
}
#define BARP(id) asm volatile("bar.sync %0, 64;" :: "r"(id) : "memory")

__device__ __forceinline__ float hfhi(float v) { return __half2float(__float2half_rn(v)); }
__device__ __forceinline__ uint32_t pkhf(float lo, float hi) {
    __half2 t = __floats2half2_rn(lo, hi);
    return *(uint32_t*)&t;
}
__device__ __forceinline__ float tanh_apx(float v) {
    float r; asm("tanh.approx.f32 %0, %1;" : "=f"(r) : "f"(v)); return r;
}
__device__ __forceinline__ float sigm_apx(float v) {
    return fmaf(0.5f, tanh_apx(0.5f * v), 0.5f);
}
__device__ __forceinline__ float sigm_ex(float v) {
    return __fdividef(1.f, 1.f + __expf(-v));
}

// ---------------- prep ----------------
__device__ __forceinline__ float getW(const float* W_ih0, const float* W_ih, const float* W_hh,
                                      int l, int n, int k) {
    if (k < 32) {
        if (l == 0) return (k < 2) ? W_ih0[n * 2 + k] : 0.f;
        return W_ih[(l - 1) * 4096 + n * 32 + k];
    }
    return W_hh[l * 4096 + n * 32 + (k - 32)];
}

__global__ void prep_kernel(const float* __restrict__ W_ih0, const float* __restrict__ W_ih,
                            const float* __restrict__ W_hh, const float* __restrict__ b_ih,
                            const float* __restrict__ b_hh, const float* __restrict__ W_lin,
                            const float* __restrict__ b_lin) {
    int i = blockIdx.x * blockDim.x + threadIdx.x;
    if (i < 16384) {
        int word = i & 1, lane = (i >> 1) & 31, nt = (i >> 6) & 15, kc = (i >> 10) & 3, l = i >> 12;
        int n  = nt * 8 + (lane >> 2);
        int k0 = kc * 16 + (lane & 3) * 2 + word * 8;
        float w0 = getW(W_ih0, W_ih, W_hh, l, n, k0);
        float w1 = getW(W_ih0, W_ih, W_hh, l, n, k0 + 1);
        __half2 t = __floats2half2_rn(w0, w1);
        gBF[i] = *(uint32_t*)&t;
    }
    if (i < 512) {
        int e = i & 1, q = (i >> 1) & 3, nt = (i >> 3) & 15, l = i >> 7;
        int n = nt * 8 + q * 2 + e;
        gBiasF[i] = b_ih[l * 128 + n] + b_hh[l * 128 + n];
    }
    if (i < 32) gWl[i] = W_lin[i];
    if (i == 0) gBl = b_lin[0];
}

// ---- one k-chunk: 4 gate n-tiles, 2-term (zhi + zlo) fp16 ----
__device__ __forceinline__ void mma_chunk(float (&d)[4][4], const uint32_t* ahi, const uint32_t* alo,
                                          uint32_t bKC, int jt) {
#pragma unroll
    for (int g4 = 0; g4 < 4; ++g4) {
        uint32_t b0, b1;
        lds64(b0, b1, bKC + (uint32_t)((g4 * 4 + jt) * 256));
        mma16816(d[g4], ahi, b0, b1);
        mma16816(d[g4], alo, b0, b1);
    }
}

// ---------------- main kernel ----------------
__global__ void __launch_bounds__(THREADS, 1)
lstm_kernel(const float* __restrict__ x, float* __restrict__ out) {
    extern __shared__ __align__(16) uint4 smemraw[];
    const uint32_t smB   = smem_u32(smemraw);
    const uint32_t biasB = smB + OFF_BIAS;
    const uint32_t hxB   = smB + OFF_HX;
    const uint32_t redB  = smB + OFF_RED;

    const int tid  = threadIdx.x;
    const int w    = tid >> 5;
    const int lane = tid & 31;
    const int q    = lane & 3;
    const int r    = lane >> 2;
    const int pp   = w >> 1;            // pair id
    const int wh   = w & 1;             // gate-col half [16wh,16wh+16); owns h chunk wh
    const int bid  = 1 + pp;            // named barrier id
    const int gb0  = blockIdx.x * ROWS_CTA + pp * 16;
    const uint32_t lane16 = (uint32_t)lane * 16u;

    // ---- stage weights + bias; zero hx ----
    {
        const uint4* src = (const uint4*)gBF;
        uint4* dst = (uint4*)smemraw;
        for (int i = tid; i < 4096; i += THREADS) dst[i] = src[i];
        float* bd = (float*)((char*)smemraw + OFF_BIAS);
        for (int i = tid; i < 512; i += THREADS) bd[i] = gBiasF[i];
        uint4* hz = (uint4*)((char*)smemraw + OFF_HX);
        for (int i = tid; i < 57344 / 16; i += THREADS) hz[i] = make_uint4(0, 0, 0, 0);
    }
    __syncthreads();
    if (gb0 >= BTOT) return;

    float cst[NL][2][4];
#pragma unroll
    for (int l = 0; l < NL; ++l)
#pragma unroll
        for (int jl = 0; jl < 2; ++jl)
#pragma unroll
            for (int p = 0; p < 4; ++p) cst[l][jl][p] = 0.f;

    float wl[2][2];
#pragma unroll
    for (int jl = 0; jl < 2; ++jl) {
        int jt = wh * 2 + jl;
        wl[jl][0] = gWl[jt * 8 + q * 2];
        wl[jl][1] = gWl[jt * 8 + q * 2 + 1];
    }

    const float* xq = x + (size_t)(gb0 + r) * 192;
    float prow0 = 0.f, prow8 = 0.f;
    const uint32_t hxPair = hxB + (uint32_t)(pp * NL * 2) * 1024u;   // no lane term (in ld/st)

#pragma unroll 1
    for (int t = 0; t < TT; ++t) {
        // ---- x fragment (layer 0, kc0): cols 0,1 live in q==0 lanes ----
        uint32_t axh[4] = {0u, 0u, 0u, 0u}, axl[4] = {0u, 0u, 0u, 0u};
        if (q == 0) {
            float x0a = __ldg(xq + t),        x1a = __ldg(xq + 64 + t);
            float x0b = __ldg(xq + 1536 + t), x1b = __ldg(xq + 1600 + t);   // row+8
            float e0 = hfhi(x0a), e1 = hfhi(x1a), e2 = hfhi(x0b), e3 = hfhi(x1b);
            axh[0] = pkhf(e0, e1);             axh[1] = pkhf(e2, e3);
            axl[0] = pkhf(x0a - e0, x1a - e1); axl[1] = pkhf(x0b - e2, x1b - e3);
        }

#pragma unroll
        for (int l = 0; l < NL; ++l) {
            const uint32_t hxL = hxPair + (uint32_t)(l * 2) * 1024u;
            uint32_t hin0[8], hin1[8], hp0[8], hp1[8];   // [0..3]=zhi frag, [4..7]=zlo frag
            if (l > 0) {
                ldfrag(hin0, hxL - 2048u, lane16);
                ldfrag(hin1, hxL - 1024u, lane16);
            }
            ldfrag(hp0, hxL,           lane16);
            ldfrag(hp1, hxL + 1024u,   lane16);

            float hh[2][4];
#pragma unroll
            for (int jl = 0; jl < 2; ++jl) {
                const int jt = wh * 2 + jl;
                float d[4][4];
#pragma unroll
                for (int g4 = 0; g4 < 4; ++g4) {
                    float2 bb = ldsf2(biasB + (uint32_t)(((l * 16 + g4 * 4 + jt) * 4 + q) * 8));
                    d[g4][0] = bb.x; d[g4][1] = bb.y; d[g4][2] = bb.x; d[g4][3] = bb.y;
                }
                const uint32_t bL = smB + (uint32_t)l * 16384u + (uint32_t)lane * 8u;
                if (l == 0) {
                    mma_chunk(d, axh, axl, bL, jt);                     // x (kc0)
                } else {
                    mma_chunk(d, hin0, hin0 + 4, bL,         jt);       // h_in kc0
                    mma_chunk(d, hin1, hin1 + 4, bL + 4096u, jt);       // h_in kc1
                }
                mma_chunk(d, hp0, hp0 + 4, bL + 8192u,  jt);            // h_prev kc2
                mma_chunk(d, hp1, hp1 + 4, bL + 12288u, jt);            // h_prev kc3

#pragma unroll
                for (int p = 0; p < 4; ++p) {
                    float ii = sigm_apx(d[0][p]);
                    float ff = sigm_apx(d[1][p]);
                    float gg = tanh_apx(d[2][p]);
                    float oo = sigm_apx(d[3][p]);
                    float cn = fmaf(ff, cst[l][jl][p], ii * gg);
                    cst[l][jl][p] = cn;
                    float hv = oo * tanh_apx(cn);
                    hh[jl][p] = hv;
                    if (l == NL - 1 && t == TT - 1) {
                        if (p == 0) prow0 = fmaf(hv, wl[jl][0], prow0);
                        if (p == 1) prow0 = fmaf(hv, wl[jl][1], prow0);
                        if (p == 2) prow8 = fmaf(hv, wl[jl][0], prow8);
                        if (p == 3) prow8 = fmaf(hv, wl[jl][1], prow8);
                    }
                }
            }

            BARP(bid);   // partner finished reading hx[l] (h_prev)
            uint32_t fr[8];
#pragma unroll
            for (int rr = 0; rr < 4; ++rr) {
                int jl = rr >> 1, p0 = (rr & 1) * 2;
                float h0 = hh[jl][p0], h1 = hh[jl][p0 + 1];
                float e0 = hfhi(h0), e1 = hfhi(h1);
                fr[rr]     = pkhf(e0, e1);
                fr[4 + rr] = pkhf(h0 - e0, h1 - e1);
            }
            stfrag(hxL + (uint32_t)wh * 1024u, lane16, fr);
            BARP(bid);   // publish h_new for next layer / next step
        }
    }

    // ---- head: out = sigmoid(h3 . Wlin + b) ----
    prow0 += __shfl_xor_sync(0xffffffffu, prow0, 1);
    prow0 += __shfl_xor_sync(0xffffffffu, prow0, 2);
    prow8 += __shfl_xor_sync(0xffffffffu, prow8, 1);
    prow8 += __shfl_xor_sync(0xffffffffu, prow8, 2);
    const uint32_t redP = redB + (uint32_t)((pp * 2 + wh) * 64);
    if (q == 0) {
        stsf(redP + (uint32_t)r * 4, prow0);
        stsf(redP + (uint32_t)(r + 8) * 4, prow8);
    }
    BARP(bid);
    if (wh == 0 && q == 0) {
        float bl = gBl;
        float v0 = ldsf(redP + (uint32_t)r * 4)       + ldsf(redP + 64u + (uint32_t)r * 4);
        float v8 = ldsf(redP + (uint32_t)(r + 8) * 4) + ldsf(redP + 64u + (uint32_t)(r + 8) * 4);
        out[gb0 + r]     = sigm_ex(v0 + bl);
        out[gb0 + r + 8] = sigm_ex(v8 + bl);
    }
}

extern "C" void kernel_launch(void* const* d_in, const int* in_sizes, int n_in,
                              void* d_out, int out_size) {
    const float* x     = (const float*)d_in[0];
    const float* W_ih0 = (const float*)d_in[1];
    const float* W_ih  = (const float*)d_in[2];
    const float* W_hh  = (const float*)d_in[3];
    const float* b_ih  = (const float*)d_in[4];
    const float* b_hh  = (const float*)d_in[5];
    const float* W_lin = (const float*)d_in[6];
    const float* b_lin = (const float*)d_in[7];

    prep_kernel<<<64, 256>>>(W_ih0, W_ih, W_hh, b_ih, b_hh, W_lin, b_lin);

    cudaFuncSetAttribute(lstm_kernel, cudaFuncAttributeMaxDynamicSharedMemorySize, DSMEM);

    int blocks = (BTOT + ROWS_CTA - 1) / ROWS_CTA;    // 147
    lstm_kernel<<<blocks, THREADS, DSMEM>>>(x, (float*)d_out);
}

// round 12
// speedup vs baseline: 2.4885x; 1.3312x over previous
#include <cuda_runtime.h>
#include <cuda_fp16.h>
#include <cstdint>

#define NL 4
#define TT 64
#define PAIRS 7
#define THREADS (PAIRS * 64)         // 448: 7 warp pairs, 16 rows each
#define ROWS_CTA (PAIRS * 16)        // 112
#define BTOT 16384

// SMEM offsets
#define OFF_BIAS 65536u
#define OFF_HX   67584u              // PAIRS * NL * 1KB = 28672 (hi-only fragments)
#define OFF_RED  96256u
#define DSMEM    (96256 + 896 + 64)

// staged data (built by prep_kernel)
__device__ uint32_t gBF[16384];      // fp16 W fragments [l][kc][nt][lane][word] (64KB)
__device__ float    gBiasF[512];
__device__ float    gWl[32];
__device__ float    gBl;

// ---------------- helpers ----------------
__device__ __forceinline__ uint32_t smem_u32(const void* p) {
    uint32_t a;
    asm("{ .reg .u64 t; cvta.to.shared.u64 t, %1; cvt.u32.u64 %0, t; }" : "=r"(a) : "l"(p));
    return a;
}
__device__ __forceinline__ void mma16816(float d[4], const uint32_t a[4], uint32_t b0, uint32_t b1) {
    asm volatile("mma.sync.aligned.m16n8k16.row.col.f32.f16.f16.f32 "
                 "{%0,%1,%2,%3}, {%4,%5,%6,%7}, {%8,%9}, {%0,%1,%2,%3};"
                 : "+f"(d[0]), "+f"(d[1]), "+f"(d[2]), "+f"(d[3])
                 : "r"(a[0]), "r"(a[1]), "r"(a[2]), "r"(a[3]), "r"(b0), "r"(b1));
}
__device__ __forceinline__ void lds64(uint32_t& a, uint32_t& b, uint32_t addr) {
    asm volatile("ld.shared.v2.u32 {%0,%1}, [%2];" : "=r"(a), "=r"(b) : "r"(addr));
}
__device__ __forceinline__ float2 ldsf2(uint32_t addr) {
    float2 v;
    asm volatile("ld.shared.v2.f32 {%0,%1}, [%2];" : "=f"(v.x), "=f"(v.y) : "r"(addr));
    return v;
}
// conflict-free 512B fragment chunk: lane stride 16B
__device__ __forceinline__ void ldf4(uint32_t* f, uint32_t addr) {
    asm volatile("ld.shared.v4.u32 {%0,%1,%2,%3}, [%4];"
                 : "=r"(f[0]), "=r"(f[1]), "=r"(f[2]), "=r"(f[3]) : "r"(addr));
}
__device__ __forceinline__ void stf4(uint32_t addr, const uint32_t* f) {
    asm volatile("st.shared.v4.u32 [%0], {%1,%2,%3,%4};"
                 :: "r"(addr), "r"(f[0]), "r"(f[1]), "r"(f[2]), "r"(f[3]) : "memory");
}
__device__ __forceinline__ void stsf(uint32_t addr, float v) {
    asm volatile("st.shared.f32 [%0], %1;" :: "r"(addr), "f"(v) : "memory");
}
__device__ __forceinline__ float ldsf(uint32_t addr) {
    float v; asm volatile("ld.shared.f32 %0, [%1];" : "=f"(v) : "r"(addr)); return v;
}
#define BARP(id) asm volatile("bar.sync %0, 64;" :: "r"(id) : "memory")

__device__ __forceinline__ uint32_t pk2h(float a, float b) {
    __half2 t = __floats2half2_rn(a, b);
    return *(uint32_t*)&t;
}
__device__ __forceinline__ uint32_t tanh2(uint32_t v) {
    uint32_t r; asm("tanh.approx.f16x2 %0, %1;" : "=r"(r) : "r"(v)); return r;
}
__device__ __forceinline__ float lo2f(uint32_t v) { return __low2float(*(__half2*)&v); }
__device__ __forceinline__ float hi2f(uint32_t v) { return __high2float(*(__half2*)&v); }
__device__ __forceinline__ uint32_t hmul2u(uint32_t a, uint32_t b) {
    __half2 r = __hmul2(*(__half2*)&a, *(__half2*)&b);
    return *(uint32_t*)&r;
}
__device__ __forceinline__ uint32_t hfma2u(uint32_t a, uint32_t b, uint32_t c) {
    __half2 r = __hfma2(*(__half2*)&a, *(__half2*)&b, *(__half2*)&c);
    return *(uint32_t*)&r;
}
__device__ __forceinline__ float sigm_ex(float v) {
    return __fdividef(1.f, 1.f + __expf(-v));
}

// ---------------- prep ----------------
__device__ __forceinline__ float getW(const float* W_ih0, const float* W_ih, const float* W_hh,
                                      int l, int n, int k) {
    if (k < 32) {
        if (l == 0) return (k < 2) ? W_ih0[n * 2 + k] : 0.f;
        return W_ih[(l - 1) * 4096 + n * 32 + k];
    }
    return W_hh[l * 4096 + n * 32 + (k - 32)];
}

__global__ void prep_kernel(const float* __restrict__ W_ih0, const float* __restrict__ W_ih,
                            const float* __restrict__ W_hh, const float* __restrict__ b_ih,
                            const float* __restrict__ b_hh, const float* __restrict__ W_lin,
                            const float* __restrict__ b_lin) {
    int i = blockIdx.x * blockDim.x + threadIdx.x;
    if (i < 16384) {
        int word = i & 1, lane = (i >> 1) & 31, nt = (i >> 6) & 15, kc = (i >> 10) & 3, l = i >> 12;
        int n  = nt * 8 + (lane >> 2);
        int k0 = kc * 16 + (lane & 3) * 2 + word * 8;
        float w0 = getW(W_ih0, W_ih, W_hh, l, n, k0);
        float w1 = getW(W_ih0, W_ih, W_hh, l, n, k0 + 1);
        __half2 t = __floats2half2_rn(w0, w1);
        gBF[i] = *(uint32_t*)&t;
    }
    if (i < 512) {
        int e = i & 1, q = (i >> 1) & 3, nt = (i >> 3) & 15, l = i >> 7;
        int n = nt * 8 + q * 2 + e;
        gBiasF[i] = b_ih[l * 128 + n] + b_hh[l * 128 + n];
    }
    if (i < 32) gWl[i] = W_lin[i];
    if (i == 0) gBl = b_lin[0];
}

// ---- one k-chunk: 4 gate n-tiles, single-term fp16 ----
__device__ __forceinline__ void mma_chunk(float (&d)[4][4], const uint32_t* a4,
                                          uint32_t bKC, int jt) {
#pragma unroll
    for (int g4 = 0; g4 < 4; ++g4) {
        uint32_t b0, b1;
        lds64(b0, b1, bKC + (uint32_t)((g4 * 4 + jt) * 256));
        mma16816(d[g4], a4, b0, b1);
    }
}

// ---------------- main kernel ----------------
__global__ void __launch_bounds__(THREADS, 1)
lstm_kernel(const float* __restrict__ x, float* __restrict__ out) {
    extern __shared__ __align__(16) uint4 smemraw[];
    const uint32_t smB   = smem_u32(smemraw);
    const uint32_t biasB = smB + OFF_BIAS;
    const uint32_t hxB   = smB + OFF_HX;
    const uint32_t redB  = smB + OFF_RED;

    const int tid  = threadIdx.x;
    const int w    = tid >> 5;
    const int lane = tid & 31;
    const int q    = lane & 3;
    const int r    = lane >> 2;
    const int pp   = w >> 1;            // pair id
    const int wh   = w & 1;             // gate-col half; owns h chunk wh
    const int bid  = 1 + pp;            // named barrier id
    const int gb0  = blockIdx.x * ROWS_CTA + pp * 16;
    const uint32_t lane16 = (uint32_t)lane * 16u;

    // ---- stage weights + bias; zero hx ----
    {
        const uint4* src = (const uint4*)gBF;
        uint4* dst = (uint4*)smemraw;
        for (int i = tid; i < 4096; i += THREADS) dst[i] = src[i];
        float* bd = (float*)((char*)smemraw + OFF_BIAS);
        for (int i = tid; i < 512; i += THREADS) bd[i] = gBiasF[i];
        uint4* hz = (uint4*)((char*)smemraw + OFF_HX);
        for (int i = tid; i < 28672 / 16; i += THREADS) hz[i] = make_uint4(0, 0, 0, 0);
    }
    __syncthreads();
    if (gb0 >= BTOT) return;

    // bias hoisted to registers: [jl][g4]
    float2 bias2[2][4];
#pragma unroll
    for (int l4 = 0; l4 < NL; ++l4) {}  // (bias is per-layer; load per-layer below instead)

    float cst[NL][2][4];
#pragma unroll
    for (int l = 0; l < NL; ++l)
#pragma unroll
        for (int jl = 0; jl < 2; ++jl)
#pragma unroll
            for (int p = 0; p < 4; ++p) cst[l][jl][p] = 0.f;

    // full bias in registers: [l][jl][g4] = 4*2*4 float2 = 64 floats is too many;
    // keep per-(jl,g4) for all layers packed as float2[NL][2][4] -> 64 regs. Acceptable? no.
    // Instead: [l][jl][g4] loaded once into 32 float2? -> compromise: keep in smem but
    // prefetch per layer into 8 regs (2jl x 4g4) -- done inside the layer loop ONCE per t? 
    // Simplest correct: hoist ALL: 4L*2jl*4g4 = 32 float2 = 64 regs -> too many.
    // Use per-layer register cache loaded outside t-loop is impossible (layer varies).
    // Keep smem ldsf2 but only ONCE per (l, jl, g4) per step as before -- replaced by: 
    // load layer bias once per layer iteration into bias2 (8 ldsf2 per layer-step, same as before).
    // To actually cut: precompute per-thread bias float2 for all (l,jl,g4): store in LOCAL array
    // of 32 float2 would spill. We accept per-layer ldsf2 (57K wf stays). Marked for R13.

    float wl[2][2];
#pragma unroll
    for (int jl = 0; jl < 2; ++jl) {
        int jt = wh * 2 + jl;
        wl[jl][0] = gWl[jt * 8 + q * 2];
        wl[jl][1] = gWl[jt * 8 + q * 2 + 1];
    }

    const float* xq = x + (size_t)(gb0 + r) * 192;
    float prow0 = 0.f, prow8 = 0.f;
    const uint32_t hxPair = hxB + (uint32_t)pp * 4096u;
    const uint32_t h05 = pk2h(0.5f, 0.5f);

#pragma unroll 1
    for (int t = 0; t < TT; ++t) {
        // ---- x fragment (layer 0, kc0): cols 0,1 live in q==0 lanes ----
        uint32_t axh[4] = {0u, 0u, 0u, 0u};
        if (q == 0) {
            float x0a = __ldg(xq + t),        x1a = __ldg(xq + 64 + t);
            float x0b = __ldg(xq + 1536 + t), x1b = __ldg(xq + 1600 + t);   // row+8
            axh[0] = pk2h(x0a, x1a);
            axh[1] = pk2h(x0b, x1b);
        }

#pragma unroll
        for (int l = 0; l < NL; ++l) {
            const uint32_t hxL = hxPair + (uint32_t)l * 1024u;
            uint32_t hin0[4], hin1[4], hp0[4], hp1[4];
            if (l > 0) {
                ldf4(hin0, hxL - 1024u + lane16);
                ldf4(hin1, hxL - 512u  + lane16);
            }
            ldf4(hp0, hxL + lane16);
            ldf4(hp1, hxL + 512u + lane16);

            uint32_t fr[4];
#pragma unroll
            for (int jl = 0; jl < 2; ++jl) {
                const int jt = wh * 2 + jl;
                float d[4][4];
#pragma unroll
                for (int g4 = 0; g4 < 4; ++g4) {
                    float2 bb = ldsf2(biasB + (uint32_t)(((l * 16 + g4 * 4 + jt) * 4 + q) * 8));
                    d[g4][0] = bb.x; d[g4][1] = bb.y; d[g4][2] = bb.x; d[g4][3] = bb.y;
                }
                const uint32_t bL = smB + (uint32_t)l * 16384u + (uint32_t)lane * 8u;
                if (l == 0) {
                    mma_chunk(d, axh, bL, jt);                     // x (kc0)
                } else {
                    mma_chunk(d, hin0, bL,         jt);            // h_in kc0
                    mma_chunk(d, hin1, bL + 4096u, jt);            // h_in kc1
                }
                mma_chunk(d, hp0, bL + 8192u,  jt);                // h_prev kc2
                mma_chunk(d, hp1, bL + 12288u, jt);                // h_prev kc3

                // ---- f16x2 epilogue: 2 cells per MUFU ----
#pragma unroll
                for (int pr = 0; pr < 2; ++pr) {
                    const int p0 = pr * 2;
                    uint32_t ti = tanh2(pk2h(0.5f * d[0][p0], 0.5f * d[0][p0 + 1]));
                    uint32_t tf = tanh2(pk2h(0.5f * d[1][p0], 0.5f * d[1][p0 + 1]));
                    uint32_t tg = tanh2(pk2h(d[2][p0],        d[2][p0 + 1]));
                    uint32_t to = tanh2(pk2h(0.5f * d[3][p0], 0.5f * d[3][p0 + 1]));
                    float i0 = fmaf(0.5f, lo2f(ti), 0.5f), i1 = fmaf(0.5f, hi2f(ti), 0.5f);
                    float f0 = fmaf(0.5f, lo2f(tf), 0.5f), f1 = fmaf(0.5f, hi2f(tf), 0.5f);
                    float g0 = lo2f(tg), g1 = hi2f(tg);
                    float c0 = fmaf(f0, cst[l][jl][p0],     i0 * g0);
                    float c1 = fmaf(f1, cst[l][jl][p0 + 1], i1 * g1);
                    cst[l][jl][p0]     = c0;
                    cst[l][jl][p0 + 1] = c1;
                    uint32_t tc = tanh2(pk2h(c0, c1));
                    uint32_t o2 = hfma2u(to, h05, h05);
                    uint32_t h2 = hmul2u(o2, tc);
                    fr[jl * 2 + pr] = h2;
                    if (l == NL - 1 && t == TT - 1) {
                        float h0v = lo2f(h2), h1v = hi2f(h2);
                        if (pr == 0) {
                            prow0 = fmaf(h0v, wl[jl][0], prow0);
                            prow0 = fmaf(h1v, wl[jl][1], prow0);
                        } else {
                            prow8 = fmaf(h0v, wl[jl][0], prow8);
                            prow8 = fmaf(h1v, wl[jl][1], prow8);
                        }
                    }
                }
            }

            BARP(bid);   // partner finished reading hx[l] (h_prev)
            stf4(hxL + (uint32_t)wh * 512u + lane16, fr);
            BARP(bid);   // publish h_new for next layer / next step
        }
    }

    // ---- head: out = sigmoid(h3 . Wlin + b) ----
    prow0 += __shfl_xor_sync(0xffffffffu, prow0, 1);
    prow0 += __shfl_xor_sync(0xffffffffu, prow0, 2);
    prow8 += __shfl_xor_sync(0xffffffffu, prow8, 1);
    prow8 += __shfl_xor_sync(0xffffffffu, prow8, 2);
    const uint32_t redP = redB + (uint32_t)((pp * 2 + wh) * 64);
    if (q == 0) {
        stsf(redP + (uint32_t)r * 4, prow0);
        stsf(redP + (uint32_t)(r + 8) * 4, prow8);
    }
    BARP(bid);
    if (wh == 0 && q == 0) {
        float bl = gBl;
        float v0 = ldsf(redP + (uint32_t)r * 4)       + ldsf(redP + 64u + (uint32_t)r * 4);
        float v8 = ldsf(redP + (uint32_t)(r + 8) * 4) + ldsf(redP + 64u + (uint32_t)(r + 8) * 4);
        out[gb0 + r]     = sigm_ex(v0 + bl);
        out[gb0 + r + 8] = sigm_ex(v8 + bl);
    }
}

extern "C" void kernel_launch(void* const* d_in, const int* in_sizes, int n_in,
                              void* d_out, int out_size) {
    const float* x     = (const float*)d_in[0];
    const float* W_ih0 = (const float*)d_in[1];
    const float* W_ih  = (const float*)d_in[2];
    const float* W_hh  = (const float*)d_in[3];
    const float* b_ih  = (const float*)d_in[4];
    const float* b_hh  = (const float*)d_in[5];
    const float* W_lin = (const float*)d_in[6];
    const float* b_lin = (const float*)d_in[7];

    prep_kernel<<<64, 256>>>(W_ih0, W_ih, W_hh, b_ih, b_hh, W_lin, b_lin);

    cudaFuncSetAttribute(lstm_kernel, cudaFuncAttributeMaxDynamicSharedMemorySize, DSMEM);

    int blocks = (BTOT + ROWS_CTA - 1) / ROWS_CTA;    // 147
    lstm_kernel<<<blocks, THREADS, DSMEM>>>(x, (float*)d_out);
}